// round 3
// baseline (speedup 1.0000x reference)
#include <cuda_runtime.h>
#include <math.h>

// GAT_15547781612261 — single persistent kernel, subgraph-pruned, aggregate-first GAT.
// edge_index / ptr are int32.

#define NN 8192
#define EE 32768
#define ET (EE + NN)
#define HH 6
#define NB 148
#define NT 512
#define TOT (NB * NT)

#define C0 1028
#define C1 128
#define C2 256
#define C3 1028
#define W1C 768
#define W2C 1536
#define W3C 6168   // = 6*1028, also the agg1 concat width

// ---------------- device globals (scratch; no allocation) ----------------
__device__ unsigned gBarCount = 0, gBarGen = 0;

__device__ int fl0[NN], fl1[NN], fl2[NN], fl3[NN];
__device__ int lst0[NN], lst1[NN], lst2[NN];
__device__ int pos0[NN], pos1[NN], pos2[NN], pos3n[NN];
__device__ int cnt[8];            // 0:M0 1:M1 2:M2 3:E1 4:E2 5:E3
__device__ int nodeB[8];
__device__ int deg1[NN], deg2[NN], deg3[NN];
__device__ int off1[NN + 1], off2[NN + 1], off3[16];
__device__ int cur1[NN], cur2[NN], cur3[8];
__device__ int e1s[ET], e1d[ET], e2s[ET], e2d[ET], e3s[ET], e3d[ET];
__device__ int csr1s[ET], csr2s[ET], csr3s[ET];
__device__ float csr1e[(size_t)ET * HH], csr2e[(size_t)ET * HH], csr3e[(size_t)ET * HH];
__device__ float z1[NN * HH], z2[NN * HH], z3[NN * HH];
__device__ float es1a[NN * HH], ed1a[NN * HH];
__device__ float es2a[NN * HH], ed2a[NN * HH];
__device__ float es3a[NN * HH], ed3a[NN * HH];
__device__ float p1s[C0 * HH], p1d[C0 * HH];
__device__ float p2s[C1 * HH], p2d[C1 * HH];
__device__ float p3s[C2 * HH], p3d[C2 * HH];
__device__ float r2s[W3C * HH], r2d[W3C * HH];       // K_cat(6168) x 6
__device__ float r3s[768 * HH], r3d[768 * HH];       // K_cat2(768) x 6
__device__ float c2s[HH], c2d[HH], c3s[HH], c3d[HH];
__device__ float agg1[(size_t)NN * W3C];             // ~202MB
__device__ float agg2[(size_t)NN * 768];             // ~25MB
__device__ float agg3[8 * 1536];
__device__ float h1v[(size_t)NN * C1];
__device__ float h2v[(size_t)NN * C2];

// ---------------- grid barrier ----------------
__device__ __forceinline__ void gridbar() {
    __syncthreads();
    if (threadIdx.x == 0) {
        __threadfence();
        unsigned g = *((volatile unsigned*)&gBarGen);
        unsigned a = atomicAdd(&gBarCount, 1u);
        if (a == (unsigned)(gridDim.x - 1)) {
            atomicExch(&gBarCount, 0u);
            atomicExch(&gBarGen, g + 1u);
        } else {
            while (*((volatile unsigned*)&gBarGen) == g) { __nanosleep(32); }
        }
        __threadfence();
    }
    __syncthreads();
}

// block-level scan: off[i] = prefix of deg[lst[i]], cur[i]=off[i], off[M]=total
__device__ void scan_offsets(const int* lst, const int* deg, int M, int* off, int* cur) {
    __shared__ int s_sum[NT];
    int tid = threadIdx.x;
    int chunk = (M + NT - 1) / NT;
    int beg = tid * chunk;
    int end = beg + chunk; if (end > M) end = M;
    int loc = 0;
    for (int i = beg; i < end && i >= 0; i++) loc += deg[lst[i]];
    s_sum[tid] = loc;
    __syncthreads();
    for (int o = 1; o < NT; o <<= 1) {
        int v = (tid >= o) ? s_sum[tid - o] : 0;
        __syncthreads();
        s_sum[tid] += v;
        __syncthreads();
    }
    int run = (tid == 0) ? 0 : s_sum[tid - 1];
    for (int i = beg; i < end && i >= 0; i++) {
        off[i] = run; cur[i] = run;
        run += deg[lst[i]];
    }
    if (tid == NT - 1) off[M] = s_sum[NT - 1];
}

__global__ __launch_bounds__(NT, 1) void gat_kernel(
    const float* __restrict__ x, const int* __restrict__ ei, const int* __restrict__ ptr,
    const float* __restrict__ W1, const float* __restrict__ as1, const float* __restrict__ ad1, const float* __restrict__ b1,
    const float* __restrict__ W2, const float* __restrict__ as2, const float* __restrict__ ad2, const float* __restrict__ b2,
    const float* __restrict__ W3, const float* __restrict__ as3, const float* __restrict__ ad3, const float* __restrict__ b3,
    float* __restrict__ out)
{
    const int tid = blockIdx.x * NT + threadIdx.x;

    // ================= P0: init + p-vectors =================
    for (int i = tid; i < NN; i += TOT) {
        int t3 = 0;
        #pragma unroll
        for (int b = 0; b < 8; b++) {
            int pv = ptr[b + 1] - 1;
            if (pv == i) { t3 = 1; pos3n[i] = b; nodeB[b] = i; }
        }
        fl3[i] = t3; fl2[i] = t3; fl1[i] = t3; fl0[i] = t3;
        deg1[i] = 0; deg2[i] = 0; deg3[i] = 0;
    }
    if (tid < 8) cnt[tid] = 0;
    for (int i = tid; i < NN * HH; i += TOT) {
        z1[i] = 0.f; z2[i] = 0.f; z3[i] = 0.f;
        es1a[i] = 0.f; ed1a[i] = 0.f; es2a[i] = 0.f;
        ed2a[i] = 0.f; es3a[i] = 0.f; ed3a[i] = 0.f;
    }
    for (int i = tid; i < NN * C1; i += TOT) h1v[i] = 0.f;
    for (size_t i = tid; i < (size_t)NN * C2; i += TOT) h2v[i] = 0.f;
    for (int i = tid; i < 8 * C3; i += TOT) out[i] = 0.f;
    // p1 (1028x6), p2 (128x6), p3 (256x6)
    for (int t = tid; t < C0 * HH; t += TOT) {
        int k = t / HH, h = t - (t / HH) * HH;
        const float* wr = &W1[(size_t)k * W1C + h * C1];
        const float* va = &as1[h * C1];
        const float* vd = &ad1[h * C1];
        float ss = 0.f, sd = 0.f;
        for (int c = 0; c < C1; c++) { float w = wr[c]; ss += w * va[c]; sd += w * vd[c]; }
        p1s[t] = ss; p1d[t] = sd;
    }
    for (int t = tid; t < C1 * HH; t += TOT) {
        int k = t / HH, h = t % HH;
        const float* wr = &W2[(size_t)k * W2C + h * C2];
        const float* va = &as2[h * C2];
        const float* vd = &ad2[h * C2];
        float ss = 0.f, sd = 0.f;
        for (int c = 0; c < C2; c++) { float w = wr[c]; ss += w * va[c]; sd += w * vd[c]; }
        p2s[t] = ss; p2d[t] = sd;
    }
    for (int t = tid; t < C2 * HH; t += TOT) {
        int k = t / HH, h = t % HH;
        const float* wr = &W3[(size_t)k * W3C + h * C3];
        const float* va = &as3[h * C3];
        const float* vd = &ad3[h * C3];
        float ss = 0.f, sd = 0.f;
        for (int c = 0; c < C3; c++) { float w = wr[c]; ss += w * va[c]; sd += w * vd[c]; }
        p3s[t] = ss; p3d[t] = sd;
    }
    gridbar();

    // ================= P1: expand level 3 + r-vectors =================
    for (int e = tid; e < EE; e += TOT) {
        int d = ei[EE + e];
        if (fl3[d]) { int s = ei[e]; fl2[s] = 1; fl1[s] = 1; fl0[s] = 1; }
    }
    // r2[K=(h,k), h2] = sum_kc W1[k, h*128+kc] * p2[kc, h2]
    for (int t = tid; t < W3C * HH; t += TOT) {
        int K = t / HH, h2 = t % HH;
        int head = K / C0, k = K % C0;
        const float* wr = &W1[(size_t)k * W1C + head * C1];
        float ss = 0.f, sd = 0.f;
        for (int kc = 0; kc < C1; kc++) { float w = wr[kc]; ss += w * p2s[kc * HH + h2]; sd += w * p2d[kc * HH + h2]; }
        r2s[t] = ss; r2d[t] = sd;
    }
    // r3[K2=(h2,k2), h3] = sum_kc W2[k2, h2*256+kc] * p3[kc, h3]
    for (int t = tid; t < 768 * HH; t += TOT) {
        int K = t / HH, h3 = t % HH;
        int head = K / C1, k = K % C1;
        const float* wr = &W2[(size_t)k * W2C + head * C2];
        float ss = 0.f, sd = 0.f;
        for (int kc = 0; kc < C2; kc++) { float w = wr[kc]; ss += w * p3s[kc * HH + h3]; sd += w * p3d[kc * HH + h3]; }
        r3s[t] = ss; r3d[t] = sd;
    }
    if (tid < HH) {
        float ss = 0.f, sd = 0.f;
        for (int kc = 0; kc < C1; kc++) { float bb = b1[kc]; ss += bb * p2s[kc * HH + tid]; sd += bb * p2d[kc * HH + tid]; }
        c2s[tid] = ss; c2d[tid] = sd;
        ss = 0.f; sd = 0.f;
        for (int kc = 0; kc < C2; kc++) { float bb = b2[kc]; ss += bb * p3s[kc * HH + tid]; sd += bb * p3d[kc * HH + tid]; }
        c3s[tid] = ss; c3d[tid] = sd;
    }
    gridbar();

    // ================= P2: expand level 2 =================
    for (int e = tid; e < EE; e += TOT) {
        int d = ei[EE + e];
        if (fl2[d]) { int s = ei[e]; fl1[s] = 1; fl0[s] = 1; }
    }
    gridbar();

    // ================= P3: expand level 1 =================
    for (int e = tid; e < EE; e += TOT) {
        int d = ei[EE + e];
        if (fl1[d]) { int s = ei[e]; fl0[s] = 1; }
    }
    gridbar();

    // ================= P4: compact + edge build + degree =================
    for (int i = tid; i < NN; i += TOT) {
        if (fl0[i]) { int j = atomicAdd(&cnt[0], 1); lst0[j] = i; pos0[i] = j; }
        if (fl1[i]) { int j = atomicAdd(&cnt[1], 1); lst1[j] = i; pos1[i] = j; }
        if (fl2[i]) { int j = atomicAdd(&cnt[2], 1); lst2[j] = i; pos2[i] = j; }
    }
    for (int t = tid; t < ET; t += TOT) {
        int s, d;
        if (t < EE) { s = ei[t]; d = ei[EE + t]; }
        else        { s = t - EE; d = t - EE; }
        if (fl1[d]) { int j = atomicAdd(&cnt[3], 1); e1s[j] = s; e1d[j] = d; atomicAdd(&deg1[d], 1); }
        if (fl2[d]) { int j = atomicAdd(&cnt[4], 1); e2s[j] = s; e2d[j] = d; atomicAdd(&deg2[d], 1); }
        if (fl3[d]) { int j = atomicAdd(&cnt[5], 1); e3s[j] = s; e3d[j] = d; atomicAdd(&deg3[d], 1); }
    }
    gridbar();

    // ================= P5: CSR scans + es1/ed1 =================
    if (blockIdx.x == 0)      scan_offsets(lst1, deg1, cnt[1], off1, cur1);
    else if (blockIdx.x == 1) scan_offsets(lst2, deg2, cnt[2], off2, cur2);
    else if (blockIdx.x == 2) scan_offsets(nodeB, deg3, 8, off3, cur3);
    else {
        int M0 = cnt[0];
        int items = M0 * HH * 4;
        int t0 = (blockIdx.x - 3) * NT + threadIdx.x;
        int stride = (NB - 3) * NT;
        for (int t = t0; t < items; t += stride) {
            int i = t / (HH * 4);
            int rem = t - i * (HH * 4);
            int h = rem >> 2, sp = rem & 3;
            int row = lst0[i];
            int k0 = sp * 257, k1 = k0 + 257; if (k1 > C0) k1 = C0;
            const float* xr = &x[(size_t)row * C0];
            float ss = 0.f, sd = 0.f;
            for (int k = k0; k < k1; k++) { float xv = xr[k]; ss += xv * p1s[k * HH + h]; sd += xv * p1d[k * HH + h]; }
            atomicAdd(&es1a[i * HH + h], ss);
            atomicAdd(&ed1a[i * HH + h], sd);
        }
    }
    gridbar();

    // ================= P6: edge1 (exp, z, CSR scatter) =================
    {
        int E1 = cnt[3];
        for (int e = tid; e < E1; e += TOT) {
            int s = e1s[e], d = e1d[e];
            int i1 = pos1[d], rs = pos0[s], rd = pos0[d];
            float ex[HH];
            #pragma unroll
            for (int h = 0; h < HH; h++) {
                float v = es1a[rs * HH + h] + ed1a[rd * HH + h];
                v = (v >= 0.f) ? v : 0.2f * v;
                ex[h] = expf(v);
                atomicAdd(&z1[i1 * HH + h], ex[h]);
            }
            int j = atomicAdd(&cur1[i1], 1);
            csr1s[j] = s;
            #pragma unroll
            for (int h = 0; h < HH; h++) csr1e[(size_t)j * HH + h] = ex[h];
        }
    }
    gridbar();

    // ================= P7: gather1 -> agg1 =================
    {
        int M1 = cnt[1];
        int items = M1 * W3C;
        for (int t = tid; t < items; t += TOT) {
            int i = t / W3C;
            int rem = t - i * W3C;
            int h = rem / C0, k = rem - (rem / C0) * C0;
            float inv = 1.0f / (6.0f * z1[i * HH + h]);
            int jb = off1[i], je = off1[i + 1];
            float acc = 0.f;
            for (int j = jb; j < je; j++)
                acc += csr1e[(size_t)j * HH + h] * x[(size_t)csr1s[j] * C0 + k];
            agg1[(size_t)i * W3C + rem] = acc * inv;
        }
    }
    gridbar();

    // ================= P8: project1 -> h1 (+b1)  and  es2/ed2 =================
    {
        int M1 = cnt[1];
        int itemsA = M1 * HH * C1;
        int itemsB = M1 * HH * 16;
        for (int t = tid; t < itemsA + itemsB; t += TOT) {
            if (t < itemsA) {
                int i = t / (HH * C1);
                int rem = t - i * (HH * C1);
                int h = rem / C1, c = rem - (rem / C1) * C1;
                const float* ar = &agg1[(size_t)i * W3C + (size_t)h * C0];
                float acc = 0.f;
                for (int k = 0; k < C0; k++) acc += ar[k] * W1[(size_t)k * W1C + h * C1 + c];
                if (h == 0) acc += b1[c];
                atomicAdd(&h1v[(size_t)i * C1 + c], acc);
            } else {
                int t2 = t - itemsA;
                int i = t2 / (HH * 16);
                int rem = t2 - i * (HH * 16);
                int h2 = rem >> 4, sp = rem & 15;
                int K0 = sp * 386, K1 = K0 + 386; if (K1 > W3C) K1 = W3C;
                const float* ar = &agg1[(size_t)i * W3C];
                float ss = (sp == 0) ? c2s[h2] : 0.f;
                float sd = (sp == 0) ? c2d[h2] : 0.f;
                for (int K = K0; K < K1; K++) { float a = ar[K]; ss += a * r2s[K * HH + h2]; sd += a * r2d[K * HH + h2]; }
                atomicAdd(&es2a[i * HH + h2], ss);
                atomicAdd(&ed2a[i * HH + h2], sd);
            }
        }
    }
    gridbar();

    // ================= P9: edge2 =================
    {
        int E2 = cnt[4];
        for (int e = tid; e < E2; e += TOT) {
            int s = e2s[e], d = e2d[e];
            int i2 = pos2[d], rs = pos1[s], rd = pos1[d];
            float ex[HH];
            #pragma unroll
            for (int h = 0; h < HH; h++) {
                float v = es2a[rs * HH + h] + ed2a[rd * HH + h];
                v = (v >= 0.f) ? v : 0.2f * v;
                ex[h] = expf(v);
                atomicAdd(&z2[i2 * HH + h], ex[h]);
            }
            int j = atomicAdd(&cur2[i2], 1);
            csr2s[j] = pos1[s];
            #pragma unroll
            for (int h = 0; h < HH; h++) csr2e[(size_t)j * HH + h] = ex[h];
        }
    }
    gridbar();

    // ================= P10: gather2 -> agg2 =================
    {
        int M2 = cnt[2];
        int items = M2 * HH * C1;   // 768 per dst
        for (int t = tid; t < items; t += TOT) {
            int i = t / (HH * C1);
            int rem = t - i * (HH * C1);
            int h = rem / C1, k = rem - (rem / C1) * C1;
            float inv = 1.0f / (6.0f * z2[i * HH + h]);
            int jb = off2[i], je = off2[i + 1];
            float acc = 0.f;
            for (int j = jb; j < je; j++)
                acc += csr2e[(size_t)j * HH + h] * h1v[(size_t)csr2s[j] * C1 + k];
            agg2[(size_t)i * 768 + rem] = acc * inv;
        }
    }
    gridbar();

    // ================= P11: project2 -> h2 (+b2)  and  es3/ed3 =================
    {
        int M2 = cnt[2];
        int itemsA = M2 * HH * C2;
        int itemsB = M2 * HH * 4;
        for (int t = tid; t < itemsA + itemsB; t += TOT) {
            if (t < itemsA) {
                int i = t / (HH * C2);
                int rem = t - i * (HH * C2);
                int h = rem / C2, c = rem - (rem / C2) * C2;
                const float* ar = &agg2[(size_t)i * 768 + (size_t)h * C1];
                float acc = 0.f;
                for (int k = 0; k < C1; k++) acc += ar[k] * W2[(size_t)k * W2C + h * C2 + c];
                if (h == 0) acc += b2[c];
                atomicAdd(&h2v[(size_t)i * C2 + c], acc);
            } else {
                int t2 = t - itemsA;
                int i = t2 / (HH * 4);
                int rem = t2 - i * (HH * 4);
                int h3 = rem >> 2, sp = rem & 3;
                int K0 = sp * 192, K1 = K0 + 192;
                const float* ar = &agg2[(size_t)i * 768];
                float ss = (sp == 0) ? c3s[h3] : 0.f;
                float sd = (sp == 0) ? c3d[h3] : 0.f;
                for (int K = K0; K < K1; K++) { float a = ar[K]; ss += a * r3s[K * HH + h3]; sd += a * r3d[K * HH + h3]; }
                atomicAdd(&es3a[i * HH + h3], ss);
                atomicAdd(&ed3a[i * HH + h3], sd);
            }
        }
    }
    gridbar();

    // ================= P12: edge3 (relu slope=0) =================
    {
        int E3 = cnt[5];
        for (int e = tid; e < E3; e += TOT) {
            int s = e3s[e], d = e3d[e];
            int i3 = pos3n[d], rs = pos2[s], rd = pos2[d];
            float ex[HH];
            #pragma unroll
            for (int h = 0; h < HH; h++) {
                float v = es3a[rs * HH + h] + ed3a[rd * HH + h];
                v = (v >= 0.f) ? v : 0.f;
                ex[h] = expf(v);
                atomicAdd(&z3[i3 * HH + h], ex[h]);
            }
            int j = atomicAdd(&cur3[i3], 1);
            csr3s[j] = pos2[s];
            #pragma unroll
            for (int h = 0; h < HH; h++) csr3e[(size_t)j * HH + h] = ex[h];
        }
    }
    gridbar();

    // ================= P13: gather3 -> agg3 =================
    {
        int items = 8 * HH * C2;   // 1536 per dst
        for (int t = tid; t < items; t += TOT) {
            int i = t / (HH * C2);
            int rem = t - i * (HH * C2);
            int h = rem / C2, k = rem - (rem / C2) * C2;
            float inv = 1.0f / (6.0f * z3[i * HH + h]);
            int jb = off3[i], je = off3[i + 1];
            float acc = 0.f;
            for (int j = jb; j < je; j++)
                acc += csr3e[(size_t)j * HH + h] * h2v[(size_t)csr3s[j] * C2 + k];
            agg3[i * 1536 + rem] = acc * inv;
        }
    }
    gridbar();

    // ================= P14: project3 + bias + residual -> out =================
    {
        int items = 8 * HH * C3;
        for (int t = tid; t < items; t += TOT) {
            int b = t / (HH * C3);
            int rem = t - b * (HH * C3);
            int h = rem / C3, c = rem - (rem / C3) * C3;
            const float* ar = &agg3[b * 1536 + h * C2];
            float acc = 0.f;
            for (int k = 0; k < C2; k++) acc += ar[k] * W3[(size_t)k * W3C + h * C3 + c];
            if (h == 0) acc += b3[c] + x[(size_t)nodeB[b] * C0 + c];
            atomicAdd(&out[b * C3 + c], acc);
        }
    }
}

// ---------------- launch ----------------
extern "C" void kernel_launch(void* const* d_in, const int* in_sizes, int n_in,
                              void* d_out, int out_size) {
    const float* x   = (const float*)d_in[0];
    const int*   ei  = (const int*)d_in[1];
    const int*   ptr = (const int*)d_in[2];
    const float* W1  = (const float*)d_in[3];
    const float* as1 = (const float*)d_in[4];
    const float* ad1 = (const float*)d_in[5];
    const float* b1  = (const float*)d_in[6];
    const float* W2  = (const float*)d_in[7];
    const float* as2 = (const float*)d_in[8];
    const float* ad2 = (const float*)d_in[9];
    const float* b2  = (const float*)d_in[10];
    const float* W3  = (const float*)d_in[11];
    const float* as3 = (const float*)d_in[12];
    const float* ad3 = (const float*)d_in[13];
    const float* b3  = (const float*)d_in[14];
    float* out = (float*)d_out;

    gat_kernel<<<NB, NT>>>(x, ei, ptr,
                           W1, as1, ad1, b1,
                           W2, as2, ad2, b2,
                           W3, as3, ad3, b3,
                           out);
}

// round 5
// speedup vs baseline: 2.2866x; 2.2866x over previous
#include <cuda_runtime.h>
#include <math.h>

// GAT_15547781612261 — 8-kernel subgraph-pruned, aggregate-first GAT.
// edge_index / ptr are int32.

#define NN 8192
#define EE 32768
#define ET (EE + NN)
#define HH 6
#define DCAP 64
#define M1CAP 8192
#define M2CAP 2048

#define C0 1028
#define C1 128
#define C2 256
#define C3 1028
#define W1C 768
#define W2C 1536
#define W3C 6168

// ---------------- device globals ----------------
__device__ int fl0[NN], fl1[NN], fl2[NN], fl3[NN];
__device__ int pos1[NN], pos2[NN];
__device__ int lst1[M1CAP], lst2[M2CAP];
__device__ int g_cnt[4];                 // 0:M1  1:M2
__device__ int nodeB[8];
__device__ int deg1[NN], deg2[NN], deg3[NN];
__device__ int bk1[NN * DCAP], bk2[NN * DCAP], bk3[NN * DCAP];
__device__ float es1a[NN * HH], ed1a[NN * HH];
__device__ float es2a[M1CAP * HH], ed2a[M1CAP * HH];
__device__ float es3a[M2CAP * HH], ed3a[M2CAP * HH];
__device__ float p1s[HH * C0], p1d[HH * C0];
__device__ float p2s[HH * C1], p2d[HH * C1];
__device__ float p3s[HH * C2], p3d[HH * C2];
__device__ float r2s[HH * W3C], r2d[HH * W3C];
__device__ float r3s[HH * 768], r3d[HH * 768];
__device__ float c2s[HH], c2d[HH], c3s[HH], c3d[HH];
__device__ float h1p[(size_t)M1CAP * HH * C1];   // per-head partials (b1 folded into h=0)
__device__ float h2p[(size_t)M2CAP * HH * C2];   // b2 folded into h=0

// ================= K1: zero + p-vectors (warp per dot) =================
__global__ void k1_init(const float* __restrict__ W1, const float* __restrict__ as1, const float* __restrict__ ad1,
                        const float* __restrict__ W2, const float* __restrict__ as2, const float* __restrict__ ad2,
                        const float* __restrict__ W3, const float* __restrict__ as3, const float* __restrict__ ad3,
                        float* __restrict__ out) {
    int tid = blockIdx.x * blockDim.x + threadIdx.x;
    int stride = gridDim.x * blockDim.x;
    for (int i = tid; i < NN; i += stride) {
        fl0[i] = 0; fl1[i] = 0; fl2[i] = 0; fl3[i] = 0;
        deg1[i] = 0; deg2[i] = 0; deg3[i] = 0;
    }
    for (int i = tid; i < NN * HH; i += stride) { es1a[i] = 0.f; ed1a[i] = 0.f; }
    for (int i = tid; i < M1CAP * HH; i += stride) { es2a[i] = 0.f; ed2a[i] = 0.f; }
    for (int i = tid; i < M2CAP * HH; i += stride) { es3a[i] = 0.f; ed3a[i] = 0.f; }
    for (int i = tid; i < 8 * C3; i += stride) out[i] = 0.f;
    if (tid < 4) g_cnt[tid] = 0;

    int w = tid >> 5, lane = tid & 31, nw = stride >> 5;
    // p1[h,k] = sum_c W1[k, h*128+c]*a[h,c]
    for (int it = w; it < HH * C0; it += nw) {
        int h = it % HH, k = it / HH;
        const float* wr = W1 + (size_t)k * W1C + h * C1;
        const float* va = as1 + h * C1;
        const float* vd = ad1 + h * C1;
        float ss = 0.f, sd = 0.f;
        #pragma unroll
        for (int j = 0; j < C1 / 32; j++) {
            int c = lane + j * 32;
            float wv = wr[c];
            ss += wv * va[c]; sd += wv * vd[c];
        }
        #pragma unroll
        for (int o = 16; o > 0; o >>= 1) { ss += __shfl_down_sync(~0u, ss, o); sd += __shfl_down_sync(~0u, sd, o); }
        if (lane == 0) { p1s[h * C0 + k] = ss; p1d[h * C0 + k] = sd; }
    }
    // p2
    for (int it = w; it < HH * C1; it += nw) {
        int h = it % HH, k = it / HH;
        const float* wr = W2 + (size_t)k * W2C + h * C2;
        const float* va = as2 + h * C2;
        const float* vd = ad2 + h * C2;
        float ss = 0.f, sd = 0.f;
        #pragma unroll
        for (int j = 0; j < C2 / 32; j++) {
            int c = lane + j * 32;
            float wv = wr[c];
            ss += wv * va[c]; sd += wv * vd[c];
        }
        #pragma unroll
        for (int o = 16; o > 0; o >>= 1) { ss += __shfl_down_sync(~0u, ss, o); sd += __shfl_down_sync(~0u, sd, o); }
        if (lane == 0) { p2s[h * C1 + k] = ss; p2d[h * C1 + k] = sd; }
    }
    // p3
    for (int it = w; it < HH * C2; it += nw) {
        int h = it % HH, k = it / HH;
        const float* wr = W3 + (size_t)k * W3C + h * C3;
        const float* va = as3 + h * C3;
        const float* vd = ad3 + h * C3;
        float ss = 0.f, sd = 0.f;
        for (int j = 0; j < 33; j++) {
            int c = lane + j * 32;
            if (c < C3) { float wv = wr[c]; ss += wv * va[c]; sd += wv * vd[c]; }
        }
        #pragma unroll
        for (int o = 16; o > 0; o >>= 1) { ss += __shfl_down_sync(~0u, ss, o); sd += __shfl_down_sync(~0u, sd, o); }
        if (lane == 0) { p3s[h * C2 + k] = ss; p3d[h * C2 + k] = sd; }
    }
}

// ================= K2: mark + expand3 + r-vectors =================
__global__ void k2_expand3(const int* __restrict__ ei, const int* __restrict__ ptr,
                           const float* __restrict__ W1, const float* __restrict__ W2,
                           const float* __restrict__ b1, const float* __restrict__ b2) {
    int tid = blockIdx.x * blockDim.x + threadIdx.x;
    int stride = gridDim.x * blockDim.x;
    if (tid < 8) {
        int node = ptr[tid + 1] - 1;
        nodeB[tid] = node;
        fl3[node] = 1; fl2[node] = 1; fl1[node] = 1; fl0[node] = 1;
    }
    int t1 = ptr[1] - 1, t2 = ptr[2] - 1, t3 = ptr[3] - 1, t4 = ptr[4] - 1;
    int t5 = ptr[5] - 1, t6 = ptr[6] - 1, t7 = ptr[7] - 1, t8 = ptr[8] - 1;
    for (int e = tid; e < EE; e += stride) {
        int d = ei[EE + e];
        if (d == t1 || d == t2 || d == t3 || d == t4 || d == t5 || d == t6 || d == t7 || d == t8) {
            int s = ei[e];
            fl2[s] = 1; fl1[s] = 1; fl0[s] = 1;
        }
    }
    int w = tid >> 5, lane = tid & 31, nw = stride >> 5;
    // r2[h2, K=(head,k)] = sum_kc W1[k, head*128+kc] * p2[h2, kc]
    for (int it = w; it < HH * W3C; it += nw) {
        int h2 = it % HH, K = it / HH;
        int head = K / C0, k = K - head * C0;
        const float* wr = W1 + (size_t)k * W1C + head * C1;
        const float* ps = p2s + h2 * C1;
        const float* pd = p2d + h2 * C1;
        float ss = 0.f, sd = 0.f;
        #pragma unroll
        for (int j = 0; j < C1 / 32; j++) {
            int c = lane + j * 32;
            float wv = wr[c];
            ss += wv * ps[c]; sd += wv * pd[c];
        }
        #pragma unroll
        for (int o = 16; o > 0; o >>= 1) { ss += __shfl_down_sync(~0u, ss, o); sd += __shfl_down_sync(~0u, sd, o); }
        if (lane == 0) { r2s[h2 * W3C + K] = ss; r2d[h2 * W3C + K] = sd; }
    }
    // r3[h3, K=(head,k)] over 768
    for (int it = w; it < HH * 768; it += nw) {
        int h3 = it % HH, K = it / HH;
        int head = K / C1, k = K - head * C1;
        const float* wr = W2 + (size_t)k * W2C + head * C2;
        const float* ps = p3s + h3 * C2;
        const float* pd = p3d + h3 * C2;
        float ss = 0.f, sd = 0.f;
        #pragma unroll
        for (int j = 0; j < C2 / 32; j++) {
            int c = lane + j * 32;
            float wv = wr[c];
            ss += wv * ps[c]; sd += wv * pd[c];
        }
        #pragma unroll
        for (int o = 16; o > 0; o >>= 1) { ss += __shfl_down_sync(~0u, ss, o); sd += __shfl_down_sync(~0u, sd, o); }
        if (lane == 0) { r3s[h3 * 768 + K] = ss; r3d[h3 * 768 + K] = sd; }
    }
    // c2[h2] = b1·p2[h2], c3[h3] = b2·p3[h3]
    for (int it = w; it < 2 * HH; it += nw) {
        int h = it % HH;
        float ss = 0.f, sd = 0.f;
        if (it < HH) {
            #pragma unroll
            for (int j = 0; j < C1 / 32; j++) {
                int c = lane + j * 32;
                float bb = b1[c];
                ss += bb * p2s[h * C1 + c]; sd += bb * p2d[h * C1 + c];
            }
        } else {
            #pragma unroll
            for (int j = 0; j < C2 / 32; j++) {
                int c = lane + j * 32;
                float bb = b2[c];
                ss += bb * p3s[h * C2 + c]; sd += bb * p3d[h * C2 + c];
            }
        }
        #pragma unroll
        for (int o = 16; o > 0; o >>= 1) { ss += __shfl_down_sync(~0u, ss, o); sd += __shfl_down_sync(~0u, sd, o); }
        if (lane == 0) {
            if (it < HH) { c2s[h] = ss; c2d[h] = sd; }
            else         { c3s[h] = ss; c3d[h] = sd; }
        }
    }
}

// ================= K3/K4: expand =================
__global__ void k3_expand2(const int* __restrict__ ei) {
    int tid = blockIdx.x * blockDim.x + threadIdx.x;
    int stride = gridDim.x * blockDim.x;
    for (int e = tid; e < EE; e += stride) {
        int d = ei[EE + e];
        if (fl2[d]) { int s = ei[e]; fl1[s] = 1; fl0[s] = 1; }
    }
}
__global__ void k4_expand1(const int* __restrict__ ei) {
    int tid = blockIdx.x * blockDim.x + threadIdx.x;
    int stride = gridDim.x * blockDim.x;
    for (int e = tid; e < EE; e += stride) {
        int d = ei[EE + e];
        if (fl1[d]) fl0[ei[e]] = 1;
    }
}

// ================= K5: compact + buckets + es1/ed1 =================
__global__ void k5_build(const int* __restrict__ ei, const float* __restrict__ x) {
    int tid = blockIdx.x * blockDim.x + threadIdx.x;
    int stride = gridDim.x * blockDim.x;
    for (int i = tid; i < NN; i += stride) {
        if (fl1[i]) { int j = atomicAdd(&g_cnt[0], 1); if (j < M1CAP) { lst1[j] = i; pos1[i] = j; } }
        if (fl2[i]) { int j = atomicAdd(&g_cnt[1], 1); if (j < M2CAP) { lst2[j] = i; pos2[i] = j; } }
    }
    for (int t = tid; t < ET; t += stride) {
        int s, d;
        if (t < EE) { s = ei[t]; d = ei[EE + t]; }
        else        { s = t - EE; d = t - EE; }
        if (fl1[d]) { int j = atomicAdd(&deg1[d], 1); if (j < DCAP) bk1[d * DCAP + j] = s; }
        if (fl2[d]) { int j = atomicAdd(&deg2[d], 1); if (j < DCAP) bk2[d * DCAP + j] = s; }
        if (fl3[d]) { int j = atomicAdd(&deg3[d], 1); if (j < DCAP) bk3[d * DCAP + j] = s; }
    }
    // es1/ed1 per (node in V0, head): warp per item
    int w = tid >> 5, lane = tid & 31, nw = stride >> 5;
    for (int it = w; it < NN * HH; it += nw) {
        int i = it / HH, h = it % HH;
        if (!fl0[i]) continue;
        const float* xr = x + (size_t)i * C0;
        const float* ps = p1s + h * C0;
        const float* pd = p1d + h * C0;
        float ss = 0.f, sd = 0.f;
        for (int j = 0; j < 33; j++) {
            int k = lane + j * 32;
            if (k < C0) { float xv = xr[k]; ss += xv * ps[k]; sd += xv * pd[k]; }
        }
        #pragma unroll
        for (int o = 16; o > 0; o >>= 1) { ss += __shfl_down_sync(~0u, ss, o); sd += __shfl_down_sync(~0u, sd, o); }
        if (lane == 0) { es1a[it] = ss; ed1a[it] = sd; }
    }
}

// ================= K6: layer-1 fused (block per (i1, h)) =================
__global__ void k6_layer1(const float* __restrict__ x, const float* __restrict__ W1,
                          const float* __restrict__ b1) {
    __shared__ float sagg[C0];
    __shared__ float sE[DCAP];
    __shared__ int   sS[DCAP];
    __shared__ float sInv;
    __shared__ float red[256];

    int M1 = g_cnt[0]; if (M1 > M1CAP) M1 = M1CAP;
    int t = threadIdx.x;
    for (int bi = blockIdx.x; bi < M1 * HH; bi += gridDim.x) {
        int i1 = bi / HH, h = bi % HH;
        int node = lst1[i1];
        int dg = deg1[node]; if (dg > DCAP) dg = DCAP;
        if (t < dg) {
            int s = bk1[node * DCAP + t];
            sS[t] = s;
            float v = es1a[s * HH + h] + ed1a[node * HH + h];
            v = (v >= 0.f) ? v : 0.2f * v;
            sE[t] = __expf(v);
        }
        __syncthreads();
        if (t == 0) {
            float z = 0.f;
            for (int j = 0; j < dg; j++) z += sE[j];
            sInv = 1.0f / (6.0f * z);
        }
        __syncthreads();
        // gather (scaled)
        float inv = sInv;
        for (int k = t; k < C0; k += 256) {
            float acc = 0.f;
            for (int j = 0; j < dg; j++)
                acc += sE[j] * x[(size_t)sS[j] * C0 + k];
            sagg[k] = acc * inv;
        }
        __syncthreads();
        // project -> h1p[i1][h][c]  (two k-halves per c, combined in smem)
        {
            int c = t & 127, half = t >> 7;
            int k0 = half * 514, k1 = k0 + 514;
            const float* wcol = W1 + h * C1 + c;
            float acc = 0.f;
            for (int k = k0; k < k1; k++)
                acc += sagg[k] * wcol[(size_t)k * W1C];
            red[t] = acc;
        }
        __syncthreads();
        if (t < C1) {
            float v = red[t] + red[t + 128];
            if (h == 0) v += b1[t];
            h1p[((size_t)i1 * HH + h) * C1 + t] = v;
        }
        // es2/ed2 partial: dot(sagg, r2[h2, h*1028 : +1028])
        for (int h2 = 0; h2 < HH; h2++) {
            const float* rs = r2s + h2 * W3C + h * C0;
            const float* rd = r2d + h2 * W3C + h * C0;
            float a = 0.f, b = 0.f;
            for (int k = t; k < C0; k += 256) {
                float sv = sagg[k];
                a += sv * rs[k]; b += sv * rd[k];
            }
            if (h == 0 && t == 0) { a += c2s[h2]; b += c2d[h2]; }
            #pragma unroll
            for (int o = 16; o > 0; o >>= 1) { a += __shfl_down_sync(~0u, a, o); b += __shfl_down_sync(~0u, b, o); }
            if ((t & 31) == 0) {
                atomicAdd(&es2a[i1 * HH + h2], a);
                atomicAdd(&ed2a[i1 * HH + h2], b);
            }
        }
        __syncthreads();
    }
}

// ================= K7: layer-2 fused (block per (i2, h)) =================
__global__ void k7_layer2(const float* __restrict__ W2, const float* __restrict__ b2) {
    __shared__ float sagg[C1];
    __shared__ float sE[DCAP];
    __shared__ int   sS[DCAP];
    __shared__ float sInv;

    int M2 = g_cnt[1]; if (M2 > M2CAP) M2 = M2CAP;
    int t = threadIdx.x;
    for (int bi = blockIdx.x; bi < M2 * HH; bi += gridDim.x) {
        int i2 = bi / HH, h = bi % HH;
        int node = lst2[i2];
        int dg = deg2[node]; if (dg > DCAP) dg = DCAP;
        int dIdx = pos1[node];
        if (t < dg) {
            int s = bk2[node * DCAP + t];
            int sIdx = pos1[s];
            sS[t] = sIdx;
            float v = es2a[sIdx * HH + h] + ed2a[dIdx * HH + h];
            v = (v >= 0.f) ? v : 0.2f * v;
            sE[t] = __expf(v);
        }
        __syncthreads();
        if (t == 0) {
            float z = 0.f;
            for (int j = 0; j < dg; j++) z += sE[j];
            sInv = 1.0f / (6.0f * z);
        }
        __syncthreads();
        float inv = sInv;
        if (t < C1) {
            int k = t;
            float acc = 0.f;
            for (int j = 0; j < dg; j++) {
                const float* hp = h1p + (size_t)sS[j] * HH * C1 + k;
                float hs = hp[0] + hp[C1] + hp[2 * C1] + hp[3 * C1] + hp[4 * C1] + hp[5 * C1];
                acc += sE[j] * hs;
            }
            sagg[k] = acc * inv;
        }
        __syncthreads();
        // project -> h2p[i2][h][c]
        {
            int c = t;
            const float* wcol = W2 + h * C2 + c;
            float acc = 0.f;
            #pragma unroll 4
            for (int k = 0; k < C1; k++)
                acc += sagg[k] * wcol[(size_t)k * W2C];
            if (h == 0) acc += b2[c];
            h2p[((size_t)i2 * HH + h) * C2 + c] = acc;
        }
        // es3/ed3 partial
        for (int h3 = 0; h3 < HH; h3++) {
            const float* rs = r3s + h3 * 768 + h * C1;
            const float* rd = r3d + h3 * 768 + h * C1;
            float a = 0.f, b = 0.f;
            if (t < C1) {
                float sv = sagg[t];
                a = sv * rs[t]; b = sv * rd[t];
            }
            if (h == 0 && t == 0) { a += c3s[h3]; b += c3d[h3]; }
            #pragma unroll
            for (int o = 16; o > 0; o >>= 1) { a += __shfl_down_sync(~0u, a, o); b += __shfl_down_sync(~0u, b, o); }
            if ((t & 31) == 0 && t < C1) {
                atomicAdd(&es3a[i2 * HH + h3], a);
                atomicAdd(&ed3a[i2 * HH + h3], b);
            }
        }
        __syncthreads();
    }
}

// ================= K8: layer-3 fused + residual (block per (b, h)) =================
__global__ void k8_layer3(const float* __restrict__ x, const float* __restrict__ W3,
                          const float* __restrict__ b3, float* __restrict__ out) {
    __shared__ float sagg[C2];
    __shared__ float sE[DCAP];
    __shared__ int   sS[DCAP];
    __shared__ float sInv;

    int t = threadIdx.x;
    for (int bi = blockIdx.x; bi < 8 * HH; bi += gridDim.x) {
        int b = bi / HH, h = bi % HH;
        int node = nodeB[b];
        int dg = deg3[node]; if (dg > DCAP) dg = DCAP;
        int dIdx = pos2[node];
        if (t < dg) {
            int s = bk3[node * DCAP + t];
            int sIdx = pos2[s];
            sS[t] = sIdx;
            float v = es3a[sIdx * HH + h] + ed3a[dIdx * HH + h];
            v = (v >= 0.f) ? v : 0.f;           // slope 0
            sE[t] = __expf(v);
        }
        __syncthreads();
        if (t == 0) {
            float z = 0.f;
            for (int j = 0; j < dg; j++) z += sE[j];
            sInv = 1.0f / (6.0f * z);
        }
        __syncthreads();
        float inv = sInv;
        if (t < C2) {
            int k = t;
            float acc = 0.f;
            for (int j = 0; j < dg; j++) {
                const float* hp = h2p + (size_t)sS[j] * HH * C2 + k;
                float hs = hp[0] + hp[C2] + hp[2 * C2] + hp[3 * C2] + hp[4 * C2] + hp[5 * C2];
                acc += sE[j] * hs;
            }
            sagg[k] = acc * inv;
        }
        __syncthreads();
        // project to 1028 outputs
        for (int c = t; c < C3; c += 256) {
            const float* wcol = W3 + h * C3 + c;
            float acc = 0.f;
            #pragma unroll 4
            for (int k = 0; k < C2; k++)
                acc += sagg[k] * wcol[(size_t)k * W3C];
            if (h == 0) acc += b3[c] + x[(size_t)node * C0 + c];
            atomicAdd(&out[b * C3 + c], acc);
        }
        __syncthreads();
    }
}

// ---------------- launch ----------------
extern "C" void kernel_launch(void* const* d_in, const int* in_sizes, int n_in,
                              void* d_out, int out_size) {
    const float* x   = (const float*)d_in[0];
    const int*   ei  = (const int*)d_in[1];
    const int*   ptr = (const int*)d_in[2];
    const float* W1  = (const float*)d_in[3];
    const float* as1 = (const float*)d_in[4];
    const float* ad1 = (const float*)d_in[5];
    const float* b1  = (const float*)d_in[6];
    const float* W2  = (const float*)d_in[7];
    const float* as2 = (const float*)d_in[8];
    const float* ad2 = (const float*)d_in[9];
    const float* b2  = (const float*)d_in[10];
    const float* W3  = (const float*)d_in[11];
    const float* as3 = (const float*)d_in[12];
    const float* ad3 = (const float*)d_in[13];
    const float* b3  = (const float*)d_in[14];
    float* out = (float*)d_out;

    k1_init<<<1024, 256>>>(W1, as1, ad1, W2, as2, ad2, W3, as3, ad3, out);
    k2_expand3<<<512, 256>>>(ei, ptr, W1, W2, b1, b2);
    k3_expand2<<<128, 256>>>(ei);
    k4_expand1<<<128, 256>>>(ei);
    k5_build<<<2048, 256>>>(ei, x);
    k6_layer1<<<2048, 256>>>(x, W1, b1);
    k7_layer2<<<512, 256>>>(W2, b2);
    k8_layer3<<<64, 256>>>(x, W3, b3, out);
}

// round 7
// speedup vs baseline: 2.5255x; 1.1045x over previous
#include <cuda_runtime.h>
#include <math.h>

// GAT_15547781612261 — 8-kernel subgraph-pruned, aggregate-first GAT.
// Round 7 (resubmit of round 6): layer-1 project tiled 8 dst-nodes/block for W1 reuse.

#define NN 8192
#define EE 32768
#define ET (EE + NN)
#define HH 6
#define DCAP 64
#define M1CAP 8192
#define M2CAP 2048
#define TILE 8

#define C0 1028
#define C1 128
#define C2 256
#define C3 1028
#define W1C 768
#define W2C 1536
#define W3C 6168

// ---------------- device globals ----------------
__device__ int fl0[NN], fl1[NN], fl2[NN], fl3[NN];
__device__ int pos1[NN], pos2[NN];
__device__ int lst1[M1CAP], lst2[M2CAP];
__device__ int g_cnt[4];                 // 0:M1  1:M2
__device__ int nodeB[8];
__device__ int deg1[NN], deg2[NN], deg3[NN];
__device__ int bk1[NN * DCAP], bk2[NN * DCAP], bk3[NN * DCAP];
__device__ float es1a[NN * HH], ed1a[NN * HH];
__device__ float es2a[M1CAP * HH], ed2a[M1CAP * HH];
__device__ float es3a[M2CAP * HH], ed3a[M2CAP * HH];
__device__ float p1s[HH * C0], p1d[HH * C0];
__device__ float p2s[HH * C1], p2d[HH * C1];
__device__ float p3s[HH * C2], p3d[HH * C2];
__device__ float r2s[HH * W3C], r2d[HH * W3C];
__device__ float r3s[HH * 768], r3d[HH * 768];
__device__ float c2s[HH], c2d[HH], c3s[HH], c3d[HH];
__device__ float h1p[(size_t)M1CAP * HH * C1];   // per-head partials (b1 folded into h=0)
__device__ float h2p[(size_t)M2CAP * HH * C2];   // b2 folded into h=0

// ================= K1: zero + p-vectors (warp per dot) =================
__global__ void k1_init(const float* __restrict__ W1, const float* __restrict__ as1, const float* __restrict__ ad1,
                        const float* __restrict__ W2, const float* __restrict__ as2, const float* __restrict__ ad2,
                        const float* __restrict__ W3, const float* __restrict__ as3, const float* __restrict__ ad3,
                        float* __restrict__ out) {
    int tid = blockIdx.x * blockDim.x + threadIdx.x;
    int stride = gridDim.x * blockDim.x;
    for (int i = tid; i < NN; i += stride) {
        fl0[i] = 0; fl1[i] = 0; fl2[i] = 0; fl3[i] = 0;
        deg1[i] = 0; deg2[i] = 0; deg3[i] = 0;
    }
    for (int i = tid; i < NN * HH; i += stride) { es1a[i] = 0.f; ed1a[i] = 0.f; }
    for (int i = tid; i < M1CAP * HH; i += stride) { es2a[i] = 0.f; ed2a[i] = 0.f; }
    for (int i = tid; i < M2CAP * HH; i += stride) { es3a[i] = 0.f; ed3a[i] = 0.f; }
    for (int i = tid; i < 8 * C3; i += stride) out[i] = 0.f;
    if (tid < 4) g_cnt[tid] = 0;

    int w = tid >> 5, lane = tid & 31, nw = stride >> 5;
    for (int it = w; it < HH * C0; it += nw) {
        int h = it % HH, k = it / HH;
        const float* wr = W1 + (size_t)k * W1C + h * C1;
        const float* va = as1 + h * C1;
        const float* vd = ad1 + h * C1;
        float ss = 0.f, sd = 0.f;
        #pragma unroll
        for (int j = 0; j < C1 / 32; j++) {
            int c = lane + j * 32;
            float wv = wr[c];
            ss += wv * va[c]; sd += wv * vd[c];
        }
        #pragma unroll
        for (int o = 16; o > 0; o >>= 1) { ss += __shfl_down_sync(~0u, ss, o); sd += __shfl_down_sync(~0u, sd, o); }
        if (lane == 0) { p1s[h * C0 + k] = ss; p1d[h * C0 + k] = sd; }
    }
    for (int it = w; it < HH * C1; it += nw) {
        int h = it % HH, k = it / HH;
        const float* wr = W2 + (size_t)k * W2C + h * C2;
        const float* va = as2 + h * C2;
        const float* vd = ad2 + h * C2;
        float ss = 0.f, sd = 0.f;
        #pragma unroll
        for (int j = 0; j < C2 / 32; j++) {
            int c = lane + j * 32;
            float wv = wr[c];
            ss += wv * va[c]; sd += wv * vd[c];
        }
        #pragma unroll
        for (int o = 16; o > 0; o >>= 1) { ss += __shfl_down_sync(~0u, ss, o); sd += __shfl_down_sync(~0u, sd, o); }
        if (lane == 0) { p2s[h * C1 + k] = ss; p2d[h * C1 + k] = sd; }
    }
    for (int it = w; it < HH * C2; it += nw) {
        int h = it % HH, k = it / HH;
        const float* wr = W3 + (size_t)k * W3C + h * C3;
        const float* va = as3 + h * C3;
        const float* vd = ad3 + h * C3;
        float ss = 0.f, sd = 0.f;
        for (int j = 0; j < 33; j++) {
            int c = lane + j * 32;
            if (c < C3) { float wv = wr[c]; ss += wv * va[c]; sd += wv * vd[c]; }
        }
        #pragma unroll
        for (int o = 16; o > 0; o >>= 1) { ss += __shfl_down_sync(~0u, ss, o); sd += __shfl_down_sync(~0u, sd, o); }
        if (lane == 0) { p3s[h * C2 + k] = ss; p3d[h * C2 + k] = sd; }
    }
}

// ================= K2: mark + expand3 + r-vectors =================
__global__ void k2_expand3(const int* __restrict__ ei, const int* __restrict__ ptr,
                           const float* __restrict__ W1, const float* __restrict__ W2,
                           const float* __restrict__ b1, const float* __restrict__ b2) {
    int tid = blockIdx.x * blockDim.x + threadIdx.x;
    int stride = gridDim.x * blockDim.x;
    if (tid < 8) {
        int node = ptr[tid + 1] - 1;
        nodeB[tid] = node;
        fl3[node] = 1; fl2[node] = 1; fl1[node] = 1; fl0[node] = 1;
    }
    int t1 = ptr[1] - 1, t2 = ptr[2] - 1, t3 = ptr[3] - 1, t4 = ptr[4] - 1;
    int t5 = ptr[5] - 1, t6 = ptr[6] - 1, t7 = ptr[7] - 1, t8 = ptr[8] - 1;
    for (int e = tid; e < EE; e += stride) {
        int d = ei[EE + e];
        if (d == t1 || d == t2 || d == t3 || d == t4 || d == t5 || d == t6 || d == t7 || d == t8) {
            int s = ei[e];
            fl2[s] = 1; fl1[s] = 1; fl0[s] = 1;
        }
    }
    int w = tid >> 5, lane = tid & 31, nw = stride >> 5;
    for (int it = w; it < HH * W3C; it += nw) {
        int h2 = it % HH, K = it / HH;
        int head = K / C0, k = K - head * C0;
        const float* wr = W1 + (size_t)k * W1C + head * C1;
        const float* ps = p2s + h2 * C1;
        const float* pd = p2d + h2 * C1;
        float ss = 0.f, sd = 0.f;
        #pragma unroll
        for (int j = 0; j < C1 / 32; j++) {
            int c = lane + j * 32;
            float wv = wr[c];
            ss += wv * ps[c]; sd += wv * pd[c];
        }
        #pragma unroll
        for (int o = 16; o > 0; o >>= 1) { ss += __shfl_down_sync(~0u, ss, o); sd += __shfl_down_sync(~0u, sd, o); }
        if (lane == 0) { r2s[h2 * W3C + K] = ss; r2d[h2 * W3C + K] = sd; }
    }
    for (int it = w; it < HH * 768; it += nw) {
        int h3 = it % HH, K = it / HH;
        int head = K / C1, k = K - head * C1;
        const float* wr = W2 + (size_t)k * W2C + head * C2;
        const float* ps = p3s + h3 * C2;
        const float* pd = p3d + h3 * C2;
        float ss = 0.f, sd = 0.f;
        #pragma unroll
        for (int j = 0; j < C2 / 32; j++) {
            int c = lane + j * 32;
            float wv = wr[c];
            ss += wv * ps[c]; sd += wv * pd[c];
        }
        #pragma unroll
        for (int o = 16; o > 0; o >>= 1) { ss += __shfl_down_sync(~0u, ss, o); sd += __shfl_down_sync(~0u, sd, o); }
        if (lane == 0) { r3s[h3 * 768 + K] = ss; r3d[h3 * 768 + K] = sd; }
    }
    for (int it = w; it < 2 * HH; it += nw) {
        int h = it % HH;
        float ss = 0.f, sd = 0.f;
        if (it < HH) {
            #pragma unroll
            for (int j = 0; j < C1 / 32; j++) {
                int c = lane + j * 32;
                float bb = b1[c];
                ss += bb * p2s[h * C1 + c]; sd += bb * p2d[h * C1 + c];
            }
        } else {
            #pragma unroll
            for (int j = 0; j < C2 / 32; j++) {
                int c = lane + j * 32;
                float bb = b2[c];
                ss += bb * p3s[h * C2 + c]; sd += bb * p3d[h * C2 + c];
            }
        }
        #pragma unroll
        for (int o = 16; o > 0; o >>= 1) { ss += __shfl_down_sync(~0u, ss, o); sd += __shfl_down_sync(~0u, sd, o); }
        if (lane == 0) {
            if (it < HH) { c2s[h] = ss; c2d[h] = sd; }
            else         { c3s[h] = ss; c3d[h] = sd; }
        }
    }
}

// ================= K3/K4: expand =================
__global__ void k3_expand2(const int* __restrict__ ei) {
    int tid = blockIdx.x * blockDim.x + threadIdx.x;
    int stride = gridDim.x * blockDim.x;
    for (int e = tid; e < EE; e += stride) {
        int d = ei[EE + e];
        if (fl2[d]) { int s = ei[e]; fl1[s] = 1; fl0[s] = 1; }
    }
}
__global__ void k4_expand1(const int* __restrict__ ei) {
    int tid = blockIdx.x * blockDim.x + threadIdx.x;
    int stride = gridDim.x * blockDim.x;
    for (int e = tid; e < EE; e += stride) {
        int d = ei[EE + e];
        if (fl1[d]) fl0[ei[e]] = 1;
    }
}

// ================= K5: compact + buckets + es1/ed1 =================
__global__ void k5_build(const int* __restrict__ ei, const float* __restrict__ x) {
    int tid = blockIdx.x * blockDim.x + threadIdx.x;
    int stride = gridDim.x * blockDim.x;
    for (int i = tid; i < NN; i += stride) {
        if (fl1[i]) { int j = atomicAdd(&g_cnt[0], 1); if (j < M1CAP) { lst1[j] = i; pos1[i] = j; } }
        if (fl2[i]) { int j = atomicAdd(&g_cnt[1], 1); if (j < M2CAP) { lst2[j] = i; pos2[i] = j; } }
    }
    for (int t = tid; t < ET; t += stride) {
        int s, d;
        if (t < EE) { s = ei[t]; d = ei[EE + t]; }
        else        { s = t - EE; d = t - EE; }
        if (fl1[d]) { int j = atomicAdd(&deg1[d], 1); if (j < DCAP) bk1[d * DCAP + j] = s; }
        if (fl2[d]) { int j = atomicAdd(&deg2[d], 1); if (j < DCAP) bk2[d * DCAP + j] = s; }
        if (fl3[d]) { int j = atomicAdd(&deg3[d], 1); if (j < DCAP) bk3[d * DCAP + j] = s; }
    }
    int w = tid >> 5, lane = tid & 31, nw = stride >> 5;
    for (int it = w; it < NN * HH; it += nw) {
        int i = it / HH, h = it % HH;
        if (!fl0[i]) continue;
        const float* xr = x + (size_t)i * C0;
        const float* ps = p1s + h * C0;
        const float* pd = p1d + h * C0;
        float ss = 0.f, sd = 0.f;
        for (int j = 0; j < 33; j++) {
            int k = lane + j * 32;
            if (k < C0) { float xv = xr[k]; ss += xv * ps[k]; sd += xv * pd[k]; }
        }
        #pragma unroll
        for (int o = 16; o > 0; o >>= 1) { ss += __shfl_down_sync(~0u, ss, o); sd += __shfl_down_sync(~0u, sd, o); }
        if (lane == 0) { es1a[it] = ss; ed1a[it] = sd; }
    }
}

// ================= K6: layer-1 fused, 8 dst-nodes per block =================
__global__ __launch_bounds__(256) void k6_layer1(const float* __restrict__ x,
                                                 const float* __restrict__ W1,
                                                 const float* __restrict__ b1) {
    __shared__ float sagg[TILE][C0];     // 32.9 KB
    __shared__ float sE[TILE][DCAP];
    __shared__ int   sS[TILE][DCAP];
    __shared__ float sInv[TILE];

    int M1 = g_cnt[0]; if (M1 > M1CAP) M1 = M1CAP;
    int nTiles = (M1 + TILE - 1) / TILE;
    int t = threadIdx.x;
    int w = t >> 5, lane = t & 31;

    for (int bi = blockIdx.x; bi < nTiles * HH; bi += gridDim.x) {
        int h = bi % HH, tile = bi / HH;
        int nValid = M1 - tile * TILE; if (nValid > TILE) nValid = TILE;

        // softmax weights: warp w -> node w
        if (w < TILE && w < nValid) {
            int node = lst1[tile * TILE + w];
            int dg = deg1[node]; if (dg > DCAP) dg = DCAP;
            float edv = ed1a[node * HH + h];
            float z = 0.f;
            for (int j = lane; j < dg; j += 32) {
                int s = bk1[node * DCAP + j];
                sS[w][j] = s;
                float v = es1a[s * HH + h] + edv;
                v = (v >= 0.f) ? v : 0.2f * v;
                float e = __expf(v);
                sE[w][j] = e;
                z += e;
            }
            #pragma unroll
            for (int o = 16; o > 0; o >>= 1) z += __shfl_down_sync(~0u, z, o);
            if (lane == 0) sInv[w] = 1.0f / (6.0f * z);
        }
        __syncthreads();

        // gather
        for (int item = t; item < nValid * C0; item += 256) {
            int n = item / C0, k = item - n * C0;
            int node = lst1[tile * TILE + n];
            int dg = deg1[node]; if (dg > DCAP) dg = DCAP;
            float acc = 0.f;
            for (int j = 0; j < dg; j++)
                acc += sE[n][j] * x[(size_t)sS[n][j] * C0 + k];
            sagg[n][k] = acc * sInv[n];
        }
        // zero tail nodes so the project loop reads defined values
        for (int item = t + nValid * C0; item < TILE * C0; item += 256)
            sagg[item / C0][item % C0] = 0.f;
        __syncthreads();

        // project: W1 element loaded once, applied to 4 nodes; two thread groups
        {
            int c = t & 127, grp = t >> 7;     // grp 0: nodes 0-3, grp 1: nodes 4-7
            int nb = grp * 4;
            const float* wcol = W1 + h * C1 + c;
            float a0 = 0.f, a1 = 0.f, a2 = 0.f, a3 = 0.f;
            for (int k = 0; k < C0; k++) {
                float wv = wcol[(size_t)k * W1C];
                a0 += sagg[nb + 0][k] * wv;
                a1 += sagg[nb + 1][k] * wv;
                a2 += sagg[nb + 2][k] * wv;
                a3 += sagg[nb + 3][k] * wv;
            }
            float bb = (h == 0) ? b1[c] : 0.f;
            if (nb + 0 < nValid) h1p[((size_t)(tile * TILE + nb + 0) * HH + h) * C1 + c] = a0 + bb;
            if (nb + 1 < nValid) h1p[((size_t)(tile * TILE + nb + 1) * HH + h) * C1 + c] = a1 + bb;
            if (nb + 2 < nValid) h1p[((size_t)(tile * TILE + nb + 2) * HH + h) * C1 + c] = a2 + bb;
            if (nb + 3 < nValid) h1p[((size_t)(tile * TILE + nb + 3) * HH + h) * C1 + c] = a3 + bb;
        }

        // es2/ed2 partials: warp per (n, h2)
        for (int item = w; item < nValid * HH; item += 8) {
            int n = item / HH, h2 = item % HH;
            const float* rs = r2s + h2 * W3C + h * C0;
            const float* rd = r2d + h2 * W3C + h * C0;
            float a = 0.f, b = 0.f;
            for (int k = lane; k < C0; k += 32) {
                float sv = sagg[n][k];
                a += sv * rs[k]; b += sv * rd[k];
            }
            #pragma unroll
            for (int o = 16; o > 0; o >>= 1) { a += __shfl_down_sync(~0u, a, o); b += __shfl_down_sync(~0u, b, o); }
            if (lane == 0) {
                if (h == 0) { a += c2s[h2]; b += c2d[h2]; }
                int i1 = tile * TILE + n;
                atomicAdd(&es2a[i1 * HH + h2], a);
                atomicAdd(&ed2a[i1 * HH + h2], b);
            }
        }
        __syncthreads();
    }
}

// ================= K7: layer-2 fused (block per (i2, h)) =================
__global__ void k7_layer2(const float* __restrict__ W2, const float* __restrict__ b2) {
    __shared__ float sagg[C1];
    __shared__ float sE[DCAP];
    __shared__ int   sS[DCAP];
    __shared__ float sInv;

    int M2 = g_cnt[1]; if (M2 > M2CAP) M2 = M2CAP;
    int t = threadIdx.x;
    for (int bi = blockIdx.x; bi < M2 * HH; bi += gridDim.x) {
        int i2 = bi / HH, h = bi % HH;
        int node = lst2[i2];
        int dg = deg2[node]; if (dg > DCAP) dg = DCAP;
        int dIdx = pos1[node];
        if (t < dg) {
            int s = bk2[node * DCAP + t];
            int sIdx = pos1[s];
            sS[t] = sIdx;
            float v = es2a[sIdx * HH + h] + ed2a[dIdx * HH + h];
            v = (v >= 0.f) ? v : 0.2f * v;
            sE[t] = __expf(v);
        }
        __syncthreads();
        if (t == 0) {
            float z = 0.f;
            for (int j = 0; j < dg; j++) z += sE[j];
            sInv = 1.0f / (6.0f * z);
        }
        __syncthreads();
        float inv = sInv;
        if (t < C1) {
            int k = t;
            float acc = 0.f;
            for (int j = 0; j < dg; j++) {
                const float* hp = h1p + (size_t)sS[j] * HH * C1 + k;
                float hs = hp[0] + hp[C1] + hp[2 * C1] + hp[3 * C1] + hp[4 * C1] + hp[5 * C1];
                acc += sE[j] * hs;
            }
            sagg[k] = acc * inv;
        }
        __syncthreads();
        {
            int c = t;
            const float* wcol = W2 + h * C2 + c;
            float acc = 0.f;
            #pragma unroll 4
            for (int k = 0; k < C1; k++)
                acc += sagg[k] * wcol[(size_t)k * W2C];
            if (h == 0) acc += b2[c];
            h2p[((size_t)i2 * HH + h) * C2 + c] = acc;
        }
        for (int h3 = 0; h3 < HH; h3++) {
            const float* rs = r3s + h3 * 768 + h * C1;
            const float* rd = r3d + h3 * 768 + h * C1;
            float a = 0.f, b = 0.f;
            if (t < C1) {
                float sv = sagg[t];
                a = sv * rs[t]; b = sv * rd[t];
            }
            if (h == 0 && t == 0) { a += c3s[h3]; b += c3d[h3]; }
            #pragma unroll
            for (int o = 16; o > 0; o >>= 1) { a += __shfl_down_sync(~0u, a, o); b += __shfl_down_sync(~0u, b, o); }
            if ((t & 31) == 0 && t < C1) {
                atomicAdd(&es3a[i2 * HH + h3], a);
                atomicAdd(&ed3a[i2 * HH + h3], b);
            }
        }
        __syncthreads();
    }
}

// ================= K8: layer-3 fused + residual (block per (b, h)) =================
__global__ void k8_layer3(const float* __restrict__ x, const float* __restrict__ W3,
                          const float* __restrict__ b3, float* __restrict__ out) {
    __shared__ float sagg[C2];
    __shared__ float sE[DCAP];
    __shared__ int   sS[DCAP];
    __shared__ float sInv;

    int t = threadIdx.x;
    for (int bi = blockIdx.x; bi < 8 * HH; bi += gridDim.x) {
        int b = bi / HH, h = bi % HH;
        int node = nodeB[b];
        int dg = deg3[node]; if (dg > DCAP) dg = DCAP;
        int dIdx = pos2[node];
        if (t < dg) {
            int s = bk3[node * DCAP + t];
            int sIdx = pos2[s];
            sS[t] = sIdx;
            float v = es3a[sIdx * HH + h] + ed3a[dIdx * HH + h];
            v = (v >= 0.f) ? v : 0.f;           // slope 0
            sE[t] = __expf(v);
        }
        __syncthreads();
        if (t == 0) {
            float z = 0.f;
            for (int j = 0; j < dg; j++) z += sE[j];
            sInv = 1.0f / (6.0f * z);
        }
        __syncthreads();
        float inv = sInv;
        if (t < C2) {
            int k = t;
            float acc = 0.f;
            for (int j = 0; j < dg; j++) {
                const float* hp = h2p + (size_t)sS[j] * HH * C2 + k;
                float hs = hp[0] + hp[C2] + hp[2 * C2] + hp[3 * C2] + hp[4 * C2] + hp[5 * C2];
                acc += sE[j] * hs;
            }
            sagg[k] = acc * inv;
        }
        __syncthreads();
        for (int c = t; c < C3; c += 256) {
            const float* wcol = W3 + h * C3 + c;
            float acc = 0.f;
            #pragma unroll 4
            for (int k = 0; k < C2; k++)
                acc += sagg[k] * wcol[(size_t)k * W3C];
            if (h == 0) acc += b3[c] + x[(size_t)node * C0 + c];
            atomicAdd(&out[b * C3 + c], acc);
        }
        __syncthreads();
    }
}

// ---------------- launch ----------------
extern "C" void kernel_launch(void* const* d_in, const int* in_sizes, int n_in,
                              void* d_out, int out_size) {
    const float* x   = (const float*)d_in[0];
    const int*   ei  = (const int*)d_in[1];
    const int*   ptr = (const int*)d_in[2];
    const float* W1  = (const float*)d_in[3];
    const float* as1 = (const float*)d_in[4];
    const float* ad1 = (const float*)d_in[5];
    const float* b1  = (const float*)d_in[6];
    const float* W2  = (const float*)d_in[7];
    const float* as2 = (const float*)d_in[8];
    const float* ad2 = (const float*)d_in[9];
    const float* b2  = (const float*)d_in[10];
    const float* W3  = (const float*)d_in[11];
    const float* as3 = (const float*)d_in[12];
    const float* ad3 = (const float*)d_in[13];
    const float* b3  = (const float*)d_in[14];
    float* out = (float*)d_out;

    k1_init<<<1024, 256>>>(W1, as1, ad1, W2, as2, ad2, W3, as3, ad3, out);
    k2_expand3<<<512, 256>>>(ei, ptr, W1, W2, b1, b2);
    k3_expand2<<<128, 256>>>(ei);
    k4_expand1<<<128, 256>>>(ei);
    k5_build<<<2048, 256>>>(ei, x);
    k6_layer1<<<256, 256>>>(x, W1, b1);
    k7_layer2<<<512, 256>>>(W2, b2);
    k8_layer3<<<64, 256>>>(x, W3, b3, out);
}